// round 16
// baseline (speedup 1.0000x reference)
#include <cuda_runtime.h>
#include <cuda_bf16.h>
#include <stdint.h>

#define BATCH 32768
#define TM    32
#define NCTA  1024
#define NT    256

// ---- smem byte offsets (per-CTA total 114816 -> 2 CTAs/SM) ----
#define PHIH 0            // phi_hi [32][512] bf16, 1024B rows, swizzled
#define PHIL 32768
#define XH   65536        // phase1: x_hi [32][128] bf16, 256B rows (8KB)
#define XL   73728
#define WH   81920        // phase1: W1 half-chunk hi (64 rows x 256B = 16KB)
#define WL   98304        // phase1: W1 half-chunk lo
#define BUFA 65536        // phase3 ping (hi 8KB @ +0, lo 8KB @ +8192)
#define BUFB 81920        // phase3 pong
#define W2H  81920        // phase2 hi (10KB)
#define W2L  98304        // phase2 lo (10KB)
#define YS   114688       // y[32] float
#define SMEM_TOTAL 114816

// ---- pre-split smem-image operand tiles (device globals: allocation-free) ----
__device__ uint4 g_xh[524288], g_xl[524288];   // [1024 blk][8KB image: 32r x 16u]
__device__ uint4 g_w1h[8192],  g_w1l[8192];    // [4 chunk][32KB image: 128r x 16u]
__device__ uint4 g_lth[32768], g_ltl[32768];   // [16 tile][32KB image] L^T[j][i]
__device__ uint4 g_w2[5120];                   // [4 chunk][hi 640 | lo 640 uint4]

// XOR swizzle for 256B/1024B-row images: 16B unit index ^ (row & 7)
__device__ __forceinline__ uint32_t swu(int row, int unit, int rb) {
    return (uint32_t)(row * rb) + (uint32_t)((unit ^ (row & 7)) << 4);
}
// quarter-tile buffer swizzle: 64B rows, 4 units; uu ^ ((row>>1)&3)
// -> 8 consecutive rows hit 8 distinct 16B segments per 128B window
__device__ __forceinline__ uint32_t swq(int row, int unit) {
    return (uint32_t)(row * 64) + (uint32_t)((unit ^ ((row >> 1) & 3)) << 4);
}
__device__ __forceinline__ void split_bf16(float v, uint32_t& h, uint32_t& l) {
    __nv_bfloat16 hb = __float2bfloat16(v);
    float r = v - __bfloat162float(hb);
    __nv_bfloat16 lb = __float2bfloat16(r);
    h = (uint32_t)__bfloat16_as_ushort(hb);
    l = (uint32_t)__bfloat16_as_ushort(lb);
}
__device__ __forceinline__ void split8(const float* v, uint4& hv, uint4& lv) {
    uint32_t hw[8], lw[8];
    #pragma unroll
    for (int q = 0; q < 8; ++q) split_bf16(v[q], hw[q], lw[q]);
    hv = make_uint4(hw[0] | (hw[1] << 16), hw[2] | (hw[3] << 16),
                    hw[4] | (hw[5] << 16), hw[6] | (hw[7] << 16));
    lv = make_uint4(lw[0] | (lw[1] << 16), lw[2] | (lw[3] << 16),
                    lw[4] | (lw[5] << 16), lw[6] | (lw[7] << 16));
}

// ---- PTX wrappers (baseline ISA, compiles for plain sm_103) ----
__device__ __forceinline__ void ldsm_x4(uint32_t a, uint32_t* r) {
    asm volatile("ldmatrix.sync.aligned.m8n8.x4.shared.b16 {%0,%1,%2,%3}, [%4];"
                 : "=r"(r[0]), "=r"(r[1]), "=r"(r[2]), "=r"(r[3]) : "r"(a));
}
__device__ __forceinline__ void ldsm_x2(uint32_t a, uint32_t* r) {
    asm volatile("ldmatrix.sync.aligned.m8n8.x2.shared.b16 {%0,%1}, [%2];"
                 : "=r"(r[0]), "=r"(r[1]) : "r"(a));
}
__device__ __forceinline__ void mma16816(float* c, const uint32_t* a, const uint32_t* b) {
    asm volatile("mma.sync.aligned.m16n8k16.row.col.f32.bf16.bf16.f32 "
                 "{%0,%1,%2,%3}, {%4,%5,%6,%7}, {%8,%9}, {%0,%1,%2,%3};"
                 : "+f"(c[0]), "+f"(c[1]), "+f"(c[2]), "+f"(c[3])
                 : "r"(a[0]), "r"(a[1]), "r"(a[2]), "r"(a[3]), "r"(b[0]), "r"(b[1]));
}
__device__ __forceinline__ void cp16(uint32_t dst, const void* src) {
    asm volatile("cp.async.ca.shared.global [%0], [%1], 16;" :: "r"(dst), "l"(src));
}
#define CP_COMMIT() asm volatile("cp.async.commit_group;" ::: "memory")
#define CP_WAIT0()  asm volatile("cp.async.wait_group 0;" ::: "memory")
#define CP_WAIT1()  asm volatile("cp.async.wait_group 1;" ::: "memory")

// ---- prep kernels ----
__global__ void prep_x(const float* __restrict__ x) {
    int u = blockIdx.x * 256 + threadIdx.x;          // 524288 units
    int rg = u >> 4, c0 = (u & 15) << 3;
    const float* s = x + (size_t)rg * 128 + c0;
    float v[8];
    #pragma unroll
    for (int q = 0; q < 8; ++q) v[q] = s[q];
    uint4 hv, lv; split8(v, hv, lv);
    uint32_t off = (uint32_t)((rg >> 5) * 512) + (swu(rg & 31, c0 >> 3, 256) >> 4);
    g_xh[off] = hv; g_xl[off] = lv;
}
__global__ void prep_rest(const float* __restrict__ W1, const float* __restrict__ Lv,
                          const float* __restrict__ W2, const float* __restrict__ qb) {
    int b = blockIdx.x;
    if (b < 32) {                                     // ---- W1 ----
        int u = b * 256 + threadIdx.x;
        int h = u >> 4, c0 = (u & 15) << 3;
        const float* s = W1 + (size_t)h * 128 + c0;
        float v[8];
        #pragma unroll
        for (int q = 0; q < 8; ++q) v[q] = s[q];
        uint4 hv, lv; split8(v, hv, lv);
        uint32_t off = ((uint32_t)((h >> 7) * 32768) + swu(h & 127, c0 >> 3, 256)) >> 4;
        g_w1h[off] = hv; g_w1l[off] = lv;
    } else if (b < 160) {                             // ---- L^T tiles ----
        int u = (b - 32) * 256 + threadIdx.x;
        int tile = u >> 11;
        int r = (u >> 4) & 127, c0 = (u & 15) << 3;
        int t = tile >> 2, kt = tile & 3;
        int j = t * 128 + r;
        float v[8];
        #pragma unroll
        for (int q = 0; q < 8; ++q) {
            int i = kt * 128 + c0 + q;
            v[q] = (j <= i) ? Lv[i * (i + 1) / 2 + j] : 0.0f;
        }
        uint4 hv, lv; split8(v, hv, lv);
        uint32_t off = ((uint32_t)(tile * 32768) + swu(r, c0 >> 3, 256)) >> 4;
        g_lth[off] = hv; g_ltl[off] = lv;
    } else {                                          // ---- W2ext ----
        int u = (b - 160) * 256 + threadIdx.x;
        if (u >= 2560) return;
        int chunk = u / 640, g = u - chunk * 640;
        int o = g >> 4, c0 = (g & 15) << 3;
        float v[8];
        #pragma unroll
        for (int q = 0; q < 8; ++q) {
            int i = chunk * 128 + c0 + q;
            v[q] = (o < 32) ? W2[(size_t)o * 512 + i] : ((o == 32) ? qb[i] : 0.0f);
        }
        uint4 hv, lv; split8(v, hv, lv);
        uint32_t off = (uint32_t)(chunk * 1280) + (swu(o, c0 >> 3, 256) >> 4);
        g_w2[off] = hv; g_w2[off + 640] = lv;
    }
}

// ---- main fused kernel: 8 warps = mw(2 m-tiles) x nh(4 B-row groups) ----
__global__ void __launch_bounds__(NT, 2)
koopman_hmma(const float* __restrict__ b1, const float* __restrict__ qc,
             float* __restrict__ out) {
    extern __shared__ char sm[];
    const int tid = threadIdx.x, lane = tid & 31, warp = tid >> 5;
    const int blk = blockIdx.x, r0 = blk * TM;
    const int mw = warp & 1, nh = warp >> 1;      // nh in 0..3
    const int m0 = mw * 16;
    const int arow = m0 + (lane & 7) + (((lane >> 3) & 1) << 3);
    const int acb  = lane >> 4;
    const int brow4 = lane & 7;
    const int bm    = lane >> 3;
    const int bku   = bm & 1;
    const int bno   = (bm >> 1) << 3;
    const int r1 = m0 + (lane >> 2), r2 = r1 + 8;
    const uint32_t smb = (uint32_t)__cvta_generic_to_shared(sm);
    float* ys = (float*)(sm + YS);

    if (tid < TM) ys[tid] = 0.0f;
    {   // stage x hi/lo (8KB each)
        const uint4* sxh = g_xh + (size_t)blk * 512;
        const uint4* sxl = g_xl + (size_t)blk * 512;
        for (int i = tid; i < 512; i += NT) {
            cp16(smb + XH + i * 16, sxh + i);
            cp16(smb + XL + i * 16, sxl + i);
        }
        CP_COMMIT();
    }

    // ============ Phase 1: phi = tanh(x @ W1^T + b1), 4 chunks x 2 halves ============
    for (int ch = 0; ch < 8; ++ch) {
        const int c = ch >> 1, hf = ch & 1;
        if (ch) __syncthreads();
        {
            const uint4* swh = g_w1h + c * 2048 + hf * 1024;
            const uint4* swl = g_w1l + c * 2048 + hf * 1024;
            for (int i = tid; i < 1024; i += NT) {
                cp16(smb + WH + i * 16, swh + i);
                cp16(smb + WL + i * 16, swl + i);
            }
            CP_COMMIT(); CP_WAIT0();
        }
        __syncthreads();

        float acc[2][4];
        #pragma unroll
        for (int nt = 0; nt < 2; ++nt)
            #pragma unroll
            for (int q = 0; q < 4; ++q) acc[nt][q] = 0.0f;

        #pragma unroll 2
        for (int k8 = 0; k8 < 8; ++k8) {
            const int ku = k8 * 2;
            uint32_t ah[4], al[4];
            uint32_t ao = smb + XH + swu(arow, ku + acb, 256);
            ldsm_x4(ao, ah);
            ldsm_x4(ao + (XL - XH), al);
            {
                int bn = nh * 16 + bno + brow4;          // 64-row half
                uint32_t bo = smb + WH + swu(bn, ku + bku, 256);
                uint32_t bh4[4], bl4[4];
                ldsm_x4(bo, bh4);
                ldsm_x4(bo + (WL - WH), bl4);
                mma16816(acc[0], ah, bh4);
                mma16816(acc[0], al, bh4);
                mma16816(acc[0], ah, bl4);
                mma16816(acc[1], ah, bh4 + 2);
                mma16816(acc[1], al, bh4 + 2);
                mma16816(acc[1], ah, bl4 + 2);
            }
        }
        // epilogue: +b1, tanh, split, store phi hi/lo
        #pragma unroll
        for (int nt = 0; nt < 2; ++nt) {
            int h = c * 128 + hf * 64 + nh * 16 + nt * 8 + (lane & 3) * 2;
            float bb0 = __ldg(b1 + h), bb1 = __ldg(b1 + h + 1);
            float v0 = tanhf(acc[nt][0] + bb0), v1 = tanhf(acc[nt][1] + bb1);
            float v2 = tanhf(acc[nt][2] + bb0), v3 = tanhf(acc[nt][3] + bb1);
            uint32_t h0, l0, h1, l1;
            uint32_t sub = ((uint32_t)(h & 7)) << 1;
            split_bf16(v0, h0, l0); split_bf16(v1, h1, l1);
            *(uint32_t*)(sm + PHIH + swu(r1, h >> 3, 1024) + sub) = h0 | (h1 << 16);
            *(uint32_t*)(sm + PHIL + swu(r1, h >> 3, 1024) + sub) = l0 | (l1 << 16);
            split_bf16(v2, h0, l0); split_bf16(v3, h1, l1);
            *(uint32_t*)(sm + PHIH + swu(r2, h >> 3, 1024) + sub) = h0 | (h1 << 16);
            *(uint32_t*)(sm + PHIL + swu(r2, h >> 3, 1024) + sub) = l0 | (l1 << 16);
        }
    }
    __syncthreads();   // phi complete; phase-3 buffers overwrite x/W regions

    // ============ Phase 3: y = ||phi @ L||^2, quarter-tile pipelined ============
    // Source images use an 8-unit XOR swizzle (unit ^ (r&7)); quarter slicing
    // must DE-SWIZZLE at the source: unit u of row r lives at index
    // r*16 + (u ^ (r&7)).  (R15 bug: linear slicing scrambled quarters for
    // rows with (r&7) >= 4.)
    for (int t = 0; t < 4; ++t) {
        float acc[4][4];
        #pragma unroll
        for (int nt = 0; nt < 4; ++nt)
            #pragma unroll
            for (int q = 0; q < 4; ++q) acc[nt][q] = 0.0f;

        const int nseq = 4 * (4 - t);
        {   // prologue: stage seq 0 (kt=t, qq=0) into BUFA
            const uint4* sh = g_lth + (size_t)(t * 4 + t) * 2048;
            const uint4* sl = g_ltl + (size_t)(t * 4 + t) * 2048;
            for (int i = tid; i < 512; i += NT) {
                int r = i >> 2, uu = i & 3;
                int si = r * 16 + (uu ^ (r & 7));          // de-swizzled source
                uint32_t d = smb + BUFA + swq(r, uu);
                cp16(d,        sh + si);
                cp16(d + 8192, sl + si);
            }
            CP_COMMIT();
        }
        for (int s = 0; s < nseq; ++s) {
            const int kt = t + (s >> 2), qq = s & 3;
            if (s + 1 < nseq) {
                const int kt2 = t + ((s + 1) >> 2), q2 = (s + 1) & 3;
                const uint32_t base2 = ((s + 1) & 1) ? BUFB : BUFA;
                const uint4* sh = g_lth + (size_t)(t * 4 + kt2) * 2048;
                const uint4* sl = g_ltl + (size_t)(t * 4 + kt2) * 2048;
                for (int i = tid; i < 512; i += NT) {
                    int r = i >> 2, uu = i & 3;
                    int si = r * 16 + ((q2 * 4 + uu) ^ (r & 7));   // de-swizzled
                    uint32_t d = smb + base2 + swq(r, uu);
                    cp16(d,        sh + si);
                    cp16(d + 8192, sl + si);
                }
                CP_COMMIT(); CP_WAIT1();
            } else {
                CP_WAIT0();
            }
            __syncthreads();

            const uint32_t hb = (s & 1) ? BUFB : BUFA;
            #pragma unroll
            for (int k8l = 0; k8l < 2; ++k8l) {
                const int kuA = kt * 16 + qq * 4 + k8l * 2;
                uint32_t ah[4], al[4];
                uint32_t ao = smb + PHIH + swu(arow, kuA + acb, 1024);
                ldsm_x4(ao, ah);
                ldsm_x4(ao + (PHIL - PHIH), al);
                #pragma unroll
                for (int ntp = 0; ntp < 2; ++ntp) {
                    int bn = nh * 32 + ntp * 16 + bno + brow4;
                    int ul = k8l * 2 + bku;
                    uint32_t bo = smb + hb + swq(bn, ul);
                    uint32_t bh4[4], bl4[4];
                    ldsm_x4(bo, bh4);
                    ldsm_x4(bo + 8192, bl4);
                    mma16816(acc[2 * ntp],     ah, bh4);
                    mma16816(acc[2 * ntp],     al, bh4);
                    mma16816(acc[2 * ntp],     ah, bl4);
                    mma16816(acc[2 * ntp + 1], ah, bh4 + 2);
                    mma16816(acc[2 * ntp + 1], al, bh4 + 2);
                    mma16816(acc[2 * ntp + 1], ah, bl4 + 2);
                }
            }
            __syncthreads();
        }
        float s1 = 0.0f, s2 = 0.0f;
        #pragma unroll
        for (int nt = 0; nt < 4; ++nt) {
            s1 = fmaf(acc[nt][0], acc[nt][0], s1);
            s1 = fmaf(acc[nt][1], acc[nt][1], s1);
            s2 = fmaf(acc[nt][2], acc[nt][2], s2);
            s2 = fmaf(acc[nt][3], acc[nt][3], s2);
        }
        s1 += __shfl_xor_sync(0xffffffffu, s1, 1);
        s1 += __shfl_xor_sync(0xffffffffu, s1, 2);
        s2 += __shfl_xor_sync(0xffffffffu, s2, 1);
        s2 += __shfl_xor_sync(0xffffffffu, s2, 2);
        if ((lane & 3) == 0) { atomicAdd(ys + r1, s1); atomicAdd(ys + r2, s2); }
    }

    // ============ Phase 2: [pi | phi.qb] = phi @ W2ext^T ============
    // 5 n-tiles over nh: nh0 -> {0,4}, nh1..3 -> {nh}
    const int ntc = (nh == 0) ? 2 : 1;
    float acc2[2][4];
    #pragma unroll
    for (int q = 0; q < 2; ++q)
        #pragma unroll
        for (int e = 0; e < 4; ++e) acc2[q][e] = 0.0f;

    for (int kt = 0; kt < 4; ++kt) {
        __syncthreads();
        {
            const uint4* s = g_w2 + kt * 1280;
            for (int i = tid; i < 640; i += NT) {
                cp16(smb + W2H + i * 16, s + i);
                cp16(smb + W2L + i * 16, s + 640 + i);
            }
            CP_COMMIT(); CP_WAIT0();
        }
        __syncthreads();
        #pragma unroll 2
        for (int k8 = 0; k8 < 8; ++k8) {
            const int kuA = kt * 16 + k8 * 2;
            const int kuB = k8 * 2;
            uint32_t ah[4], al[4];
            uint32_t ao = smb + PHIH + swu(arow, kuA + acb, 1024);
            ldsm_x4(ao, ah);
            ldsm_x4(ao + (PHIL - PHIH), al);
            #pragma unroll
            for (int q = 0; q < 2; ++q) {
                if (q >= ntc) break;
                int tile = (q == 0) ? nh : 4;
                uint32_t bo = smb + W2H + swu(tile * 8 + (lane & 7), kuB + ((lane >> 3) & 1), 256);
                uint32_t bh[2], bl[2];
                ldsm_x2(bo, bh);
                ldsm_x2(bo + (W2L - W2H), bl);
                mma16816(acc2[q], ah, bh);
                mma16816(acc2[q], al, bh);
                mma16816(acc2[q], ah, bl);
            }
        }
    }
    __syncthreads();
    #pragma unroll
    for (int q = 0; q < 2; ++q) {
        if (q >= ntc) break;
        int tile = (q == 0) ? nh : 4;
        int o = tile * 8 + (lane & 3) * 2;
        if (tile < 4) {
            out[(size_t)(r0 + r1) * 32 + o]     = acc2[q][0];
            out[(size_t)(r0 + r1) * 32 + o + 1] = acc2[q][1];
            out[(size_t)(r0 + r2) * 32 + o]     = acc2[q][2];
            out[(size_t)(r0 + r2) * 32 + o + 1] = acc2[q][3];
        } else if ((lane & 3) == 0) {
            float qcv = __ldg(qc);
            out[(size_t)BATCH * 32 + r0 + r1] = ys[r1] + acc2[q][0] + qcv;
            out[(size_t)BATCH * 32 + r0 + r2] = ys[r2] + acc2[q][2] + qcv;
        }
    }
}

// ---------------------------------------------------------------------------
extern "C" void kernel_launch(void* const* d_in, const int* in_sizes, int n_in,
                              void* d_out, int out_size) {
    const float* x  = (const float*)d_in[0];
    const float* W1 = (const float*)d_in[1];
    const float* b1 = (const float*)d_in[2];
    const float* W2 = (const float*)d_in[3];
    const float* Lv = (const float*)d_in[4];
    const float* qb = (const float*)d_in[5];
    const float* qc = (const float*)d_in[6];
    float* out = (float*)d_out;

    // Attribute set only on the (non-captured) first call — runtime APIs
    // during graph capture kill the capture (R5/R7 lesson).
    static bool attr_done = false;
    if (!attr_done) {
        cudaFuncSetAttribute(koopman_hmma,
                             cudaFuncAttributeMaxDynamicSharedMemorySize,
                             SMEM_TOTAL);
        attr_done = true;
    }

    prep_x   <<<2048, 256>>>(x);
    prep_rest<<<170,  256>>>(W1, Lv, W2, qb);
    koopman_hmma<<<NCTA, NT, SMEM_TOTAL>>>(b1, qc, out);
}

// round 17
// speedup vs baseline: 1.1013x; 1.1013x over previous
#include <cuda_runtime.h>
#include <cuda_bf16.h>
#include <stdint.h>

#define BATCH 32768
#define TM    64
#define NCTA  512
#define NT    256

// ---- smem byte offsets ----
#define PHIH 0            // phi_hi [64][512] bf16, 1024B rows, swizzled
#define PHIL 65536
#define XH   131072       // phase1: x_hi [64][128] bf16, 256B rows
#define XL   147456
#define WH   163840       // phase1: W1 staging hi (128 rows x 256B)
#define WL   196608       // phase1: W1 staging lo
#define BUFA 131072       // phase3 ping buffer (hi 16K + lo 16K)
#define BUFB 163840       // phase3 pong buffer (hi 16K + lo 16K)
#define W2LO (WH + 10240) // phase-2 lo region (40 rows x 256B)
#define YS   229376       // y[64] float
#define SMEM_TOTAL 229632

// ---- pre-split smem-image operand tiles (device globals: allocation-free) ----
__device__ uint4 g_xh[524288], g_xl[524288];   // [512 blk][16KB image]
__device__ uint4 g_w1h[8192],  g_w1l[8192];    // [4 chunk][32KB image]
__device__ uint4 g_lth[32768], g_ltl[32768];   // [16 tile][32KB image] L^T[j][i]
__device__ uint4 g_w2[5120];                   // [4 chunk][hi 10KB | lo 10KB]

// XOR swizzle: 16B unit index ^ (row & 7); conflict-free ldmatrix
__device__ __forceinline__ uint32_t swu(int row, int unit, int rb) {
    return (uint32_t)(row * rb) + (uint32_t)((unit ^ (row & 7)) << 4);
}
__device__ __forceinline__ void split_bf16(float v, uint32_t& h, uint32_t& l) {
    __nv_bfloat16 hb = __float2bfloat16(v);
    float r = v - __bfloat162float(hb);
    __nv_bfloat16 lb = __float2bfloat16(r);
    h = (uint32_t)__bfloat16_as_ushort(hb);
    l = (uint32_t)__bfloat16_as_ushort(lb);
}
__device__ __forceinline__ void split8(const float* v, uint4& hv, uint4& lv) {
    uint32_t hw[8], lw[8];
    #pragma unroll
    for (int q = 0; q < 8; ++q) split_bf16(v[q], hw[q], lw[q]);
    hv = make_uint4(hw[0] | (hw[1] << 16), hw[2] | (hw[3] << 16),
                    hw[4] | (hw[5] << 16), hw[6] | (hw[7] << 16));
    lv = make_uint4(lw[0] | (lw[1] << 16), lw[2] | (lw[3] << 16),
                    lw[4] | (lw[5] << 16), lw[6] | (lw[7] << 16));
}

// ---- PTX wrappers (baseline ISA, compiles for plain sm_103) ----
__device__ __forceinline__ void ldsm_x4(uint32_t a, uint32_t* r) {
    asm volatile("ldmatrix.sync.aligned.m8n8.x4.shared.b16 {%0,%1,%2,%3}, [%4];"
                 : "=r"(r[0]), "=r"(r[1]), "=r"(r[2]), "=r"(r[3]) : "r"(a));
}
__device__ __forceinline__ void ldsm_x2(uint32_t a, uint32_t* r) {
    asm volatile("ldmatrix.sync.aligned.m8n8.x2.shared.b16 {%0,%1}, [%2];"
                 : "=r"(r[0]), "=r"(r[1]) : "r"(a));
}
__device__ __forceinline__ void mma16816(float* c, const uint32_t* a, const uint32_t* b) {
    asm volatile("mma.sync.aligned.m16n8k16.row.col.f32.bf16.bf16.f32 "
                 "{%0,%1,%2,%3}, {%4,%5,%6,%7}, {%8,%9}, {%0,%1,%2,%3};"
                 : "+f"(c[0]), "+f"(c[1]), "+f"(c[2]), "+f"(c[3])
                 : "r"(a[0]), "r"(a[1]), "r"(a[2]), "r"(a[3]), "r"(b[0]), "r"(b[1]));
}
__device__ __forceinline__ void cp16(uint32_t dst, const void* src) {
    asm volatile("cp.async.ca.shared.global [%0], [%1], 16;" :: "r"(dst), "l"(src));
}
#define CP_COMMIT() asm volatile("cp.async.commit_group;" ::: "memory")
#define CP_WAIT0()  asm volatile("cp.async.wait_group 0;" ::: "memory")
#define CP_WAIT1()  asm volatile("cp.async.wait_group 1;" ::: "memory")

// ---- prep kernels ----
__global__ void prep_x(const float* __restrict__ x) {
    int u = blockIdx.x * 256 + threadIdx.x;          // 524288 units
    int rg = u >> 4, c0 = (u & 15) << 3;
    const float* s = x + (size_t)rg * 128 + c0;
    float v[8];
    #pragma unroll
    for (int q = 0; q < 8; ++q) v[q] = s[q];
    uint4 hv, lv; split8(v, hv, lv);
    uint32_t off = ((uint32_t)((rg >> 6) * 16384) + swu(rg & 63, c0 >> 3, 256)) >> 4;
    g_xh[off] = hv; g_xl[off] = lv;
}
__global__ void prep_rest(const float* __restrict__ W1, const float* __restrict__ Lv,
                          const float* __restrict__ W2, const float* __restrict__ qb) {
    int b = blockIdx.x;
    if (b < 32) {                                     // ---- W1 ----
        int u = b * 256 + threadIdx.x;
        int h = u >> 4, c0 = (u & 15) << 3;
        const float* s = W1 + (size_t)h * 128 + c0;
        float v[8];
        #pragma unroll
        for (int q = 0; q < 8; ++q) v[q] = s[q];
        uint4 hv, lv; split8(v, hv, lv);
        uint32_t off = ((uint32_t)((h >> 7) * 32768) + swu(h & 127, c0 >> 3, 256)) >> 4;
        g_w1h[off] = hv; g_w1l[off] = lv;
    } else if (b < 160) {                             // ---- L^T tiles ----
        int u = (b - 32) * 256 + threadIdx.x;
        int tile = u >> 11;
        int r = (u >> 4) & 127, c0 = (u & 15) << 3;
        int t = tile >> 2, kt = tile & 3;
        int j = t * 128 + r;
        float v[8];
        #pragma unroll
        for (int q = 0; q < 8; ++q) {
            int i = kt * 128 + c0 + q;
            v[q] = (j <= i) ? Lv[i * (i + 1) / 2 + j] : 0.0f;
        }
        uint4 hv, lv; split8(v, hv, lv);
        uint32_t off = ((uint32_t)(tile * 32768) + swu(r, c0 >> 3, 256)) >> 4;
        g_lth[off] = hv; g_ltl[off] = lv;
    } else {                                          // ---- W2ext ----
        int u = (b - 160) * 256 + threadIdx.x;
        if (u >= 2560) return;
        int chunk = u / 640, g = u - chunk * 640;
        int o = g >> 4, c0 = (g & 15) << 3;
        float v[8];
        #pragma unroll
        for (int q = 0; q < 8; ++q) {
            int i = chunk * 128 + c0 + q;
            v[q] = (o < 32) ? W2[(size_t)o * 512 + i] : ((o == 32) ? qb[i] : 0.0f);
        }
        uint4 hv, lv; split8(v, hv, lv);
        uint32_t off = (uint32_t)(chunk * 1280) + (swu(o, c0 >> 3, 256) >> 4);
        g_w2[off] = hv; g_w2[off + 640] = lv;
    }
}

// ---- main fused kernel: 8 warps = mw(4 m-tiles) x nh(2 B-row halves) ----
__global__ void __launch_bounds__(NT, 1)
koopman_hmma(const float* __restrict__ b1, const float* __restrict__ qc,
             float* __restrict__ out) {
    extern __shared__ char sm[];
    const int tid = threadIdx.x, lane = tid & 31, warp = tid >> 5;
    const int blk = blockIdx.x, r0 = blk * TM;
    const int mw = warp & 3, nh = warp >> 2;
    const int m0 = mw * 16;
    const int arow = m0 + (lane & 7) + (((lane >> 3) & 1) << 3);
    const int acb  = lane >> 4;
    // B-operand x4 pairing: lane group m = lane>>3 -> matrix m
    const int brow4 = lane & 7;
    const int bm    = lane >> 3;
    const int bku   = bm & 1;          // k-unit select within pair
    const int bno   = (bm >> 1) << 3;  // +8 rows for second n-tile
    const int r1 = m0 + (lane >> 2), r2 = r1 + 8;
    const uint32_t smb = (uint32_t)__cvta_generic_to_shared(sm);
    float* ys = (float*)(sm + YS);

    if (tid < TM) ys[tid] = 0.0f;
    {   // stage x hi/lo via cp.async
        const uint4* sxh = g_xh + (size_t)blk * 1024;
        const uint4* sxl = g_xl + (size_t)blk * 1024;
        for (int i = tid; i < 1024; i += NT) {
            cp16(smb + XH + i * 16, sxh + i);
            cp16(smb + XL + i * 16, sxl + i);
        }
        CP_COMMIT();
    }

    // ============ Phase 1: phi = tanh(x @ W1^T + b1) ============
    for (int c = 0; c < 4; ++c) {
        if (c) __syncthreads();
        {
            const uint4* swh = g_w1h + c * 2048;
            const uint4* swl = g_w1l + c * 2048;
            for (int i = tid; i < 2048; i += NT) {
                cp16(smb + WH + i * 16, swh + i);
                cp16(smb + WL + i * 16, swl + i);
            }
            CP_COMMIT(); CP_WAIT0();
        }
        __syncthreads();

        float acc[8][4];
        #pragma unroll
        for (int nt = 0; nt < 8; ++nt)
            #pragma unroll
            for (int q = 0; q < 4; ++q) acc[nt][q] = 0.0f;

        #pragma unroll 2
        for (int k8 = 0; k8 < 8; ++k8) {
            const int ku = k8 * 2;
            uint32_t ah[4], al[4];
            uint32_t ao = smb + XH + swu(arow, ku + acb, 256);
            ldsm_x4(ao, ah);
            ldsm_x4(ao + (XL - XH), al);
            #pragma unroll
            for (int ntp = 0; ntp < 4; ++ntp) {
                int bn = nh * 64 + ntp * 16 + bno + brow4;
                uint32_t bo = smb + WH + swu(bn, ku + bku, 256);
                uint32_t bh4[4], bl4[4];
                ldsm_x4(bo, bh4);
                ldsm_x4(bo + (WL - WH), bl4);
                mma16816(acc[2 * ntp],     ah, bh4);
                mma16816(acc[2 * ntp],     al, bh4);
                mma16816(acc[2 * ntp],     ah, bl4);
                mma16816(acc[2 * ntp + 1], ah, bh4 + 2);
                mma16816(acc[2 * ntp + 1], al, bh4 + 2);
                mma16816(acc[2 * ntp + 1], ah, bl4 + 2);
            }
        }
        // epilogue: +b1, tanh, split, store phi hi/lo
        #pragma unroll
        for (int nt = 0; nt < 8; ++nt) {
            int h = c * 128 + nh * 64 + nt * 8 + (lane & 3) * 2;
            float bb0 = __ldg(b1 + h), bb1 = __ldg(b1 + h + 1);
            float v0 = tanhf(acc[nt][0] + bb0), v1 = tanhf(acc[nt][1] + bb1);
            float v2 = tanhf(acc[nt][2] + bb0), v3 = tanhf(acc[nt][3] + bb1);
            uint32_t h0, l0, h1, l1;
            uint32_t sub = ((uint32_t)(h & 7)) << 1;
            split_bf16(v0, h0, l0); split_bf16(v1, h1, l1);
            *(uint32_t*)(sm + PHIH + swu(r1, h >> 3, 1024) + sub) = h0 | (h1 << 16);
            *(uint32_t*)(sm + PHIL + swu(r1, h >> 3, 1024) + sub) = l0 | (l1 << 16);
            split_bf16(v2, h0, l0); split_bf16(v3, h1, l1);
            *(uint32_t*)(sm + PHIH + swu(r2, h >> 3, 1024) + sub) = h0 | (h1 << 16);
            *(uint32_t*)(sm + PHIL + swu(r2, h >> 3, 1024) + sub) = l0 | (l1 << 16);
        }
    }
    __syncthreads();   // phi complete; phase-3 buffers may overwrite x/W regions

    // ============ Phase 3: y = ||phi @ L||^2, half-tile pipelined ============
    // Fragment-level triangular skip on diagonal tiles (kt == t):
    //   B fragment rows rg*16..+16 (j-local), cols ci*16..+16 (i-local) are
    //   all zero iff rg > ci  (L^T[j][i]=0 for j > i).  Interleaved row
    //   mapping rg = ntp*2 + nh balances the skips across the nh halves.
    for (int t = 0; t < 4; ++t) {
        float acc[8][4];
        #pragma unroll
        for (int nt = 0; nt < 8; ++nt)
            #pragma unroll
            for (int q = 0; q < 4; ++q) acc[nt][q] = 0.0f;

        const int nseq = 2 * (4 - t);
        {   // prologue: stage seq 0 into BUFA
            const uint4* sh = g_lth + (size_t)(t * 4 + t) * 2048;
            const uint4* sl = g_ltl + (size_t)(t * 4 + t) * 2048;
            for (int i = tid; i < 1024; i += NT) {
                int r = i >> 3, uu = i & 7;
                uint32_t d = smb + BUFA + (uint32_t)(r * 128 + uu * 16);
                cp16(d,         sh + r * 16 + uu);
                cp16(d + 16384, sl + r * 16 + uu);
            }
            CP_COMMIT();
        }
        for (int s = 0; s < nseq; ++s) {
            const int kt = t + (s >> 1), half = s & 1;
            if (s + 1 < nseq) {
                const int kt2 = t + ((s + 1) >> 1), h2 = (s + 1) & 1;
                const uint32_t base2 = ((s + 1) & 1) ? BUFB : BUFA;
                const uint4* sh = g_lth + (size_t)(t * 4 + kt2) * 2048;
                const uint4* sl = g_ltl + (size_t)(t * 4 + kt2) * 2048;
                for (int i = tid; i < 1024; i += NT) {
                    int r = i >> 3, uu = i & 7;
                    uint32_t d = smb + base2 + (uint32_t)(r * 128 + uu * 16);
                    cp16(d,         sh + r * 16 + h2 * 8 + uu);
                    cp16(d + 16384, sl + r * 16 + h2 * 8 + uu);
                }
                CP_COMMIT(); CP_WAIT1();
            } else {
                CP_WAIT0();
            }
            __syncthreads();

            const uint32_t hb = (s & 1) ? BUFB : BUFA;
            const bool diag = (kt == t);
            #pragma unroll
            for (int k8l = 0; k8l < 4; ++k8l) {
                const int ci = half * 4 + k8l;           // 16-col group index
                if (diag && nh > ci) continue;           // all fragments zero for this warp
                const int kuA = kt * 16 + ci * 2;
                uint32_t ah[4], al[4];
                uint32_t ao = smb + PHIH + swu(arow, kuA + acb, 1024);
                ldsm_x4(ao, ah);
                ldsm_x4(ao + (PHIL - PHIH), al);
                #pragma unroll
                for (int ntp = 0; ntp < 4; ++ntp) {
                    const int rg = ntp * 2 + nh;         // interleaved 16-row group
                    if (diag && rg > ci) continue;       // zero fragment: skip
                    int bn = rg * 16 + bno + brow4;
                    uint32_t up = (uint32_t)(k8l * 2 + bku);
                    uint32_t bo = smb + hb + (uint32_t)(bn * 128) +
                                  ((up ^ (uint32_t)(bn & 7)) << 4);
                    uint32_t bh4[4], bl4[4];
                    ldsm_x4(bo, bh4);
                    ldsm_x4(bo + 16384, bl4);
                    mma16816(acc[2 * ntp],     ah, bh4);
                    mma16816(acc[2 * ntp],     al, bh4);
                    mma16816(acc[2 * ntp],     ah, bl4);
                    mma16816(acc[2 * ntp + 1], ah, bh4 + 2);
                    mma16816(acc[2 * ntp + 1], al, bh4 + 2);
                    mma16816(acc[2 * ntp + 1], ah, bl4 + 2);
                }
            }
            __syncthreads();
        }
        float s1 = 0.0f, s2 = 0.0f;
        #pragma unroll
        for (int nt = 0; nt < 8; ++nt) {
            s1 = fmaf(acc[nt][0], acc[nt][0], s1);
            s1 = fmaf(acc[nt][1], acc[nt][1], s1);
            s2 = fmaf(acc[nt][2], acc[nt][2], s2);
            s2 = fmaf(acc[nt][3], acc[nt][3], s2);
        }
        s1 += __shfl_xor_sync(0xffffffffu, s1, 1);
        s1 += __shfl_xor_sync(0xffffffffu, s1, 2);
        s2 += __shfl_xor_sync(0xffffffffu, s2, 1);
        s2 += __shfl_xor_sync(0xffffffffu, s2, 2);
        if ((lane & 3) == 0) { atomicAdd(ys + r1, s1); atomicAdd(ys + r2, s2); }
    }

    // ============ Phase 2: [pi | phi.qb] = phi @ W2ext^T ============
    const int ntc = nh ? 2 : 3;
    float acc2[3][4];
    #pragma unroll
    for (int q = 0; q < 3; ++q)
        #pragma unroll
        for (int e = 0; e < 4; ++e) acc2[q][e] = 0.0f;

    for (int kt = 0; kt < 4; ++kt) {
        __syncthreads();
        {
            const uint4* s = g_w2 + kt * 1280;
            for (int i = tid; i < 640; i += NT) {
                cp16(smb + WH   + i * 16, s + i);
                cp16(smb + W2LO + i * 16, s + 640 + i);
            }
            CP_COMMIT(); CP_WAIT0();
        }
        __syncthreads();
        #pragma unroll 2
        for (int k8 = 0; k8 < 8; ++k8) {
            const int kuA = (kt * 128 + k8 * 16) >> 3;
            const int kuB = k8 * 2;
            uint32_t ah[4], al[4];
            uint32_t ao = smb + PHIH + swu(arow, kuA + acb, 1024);
            ldsm_x4(ao, ah);
            ldsm_x4(ao + (PHIL - PHIH), al);
            #pragma unroll
            for (int q = 0; q < 3; ++q) {
                if (q >= ntc) break;
                int tile = nh ? 3 + q : q;
                uint32_t bo = smb + WH + swu(tile * 8 + (lane & 7), kuB + ((lane >> 3) & 1), 256);
                uint32_t bh[2], bl[2];
                ldsm_x2(bo, bh);
                ldsm_x2(bo + (W2LO - WH), bl);
                mma16816(acc2[q], ah, bh);
                mma16816(acc2[q], al, bh);
                mma16816(acc2[q], ah, bl);
            }
        }
    }
    __syncthreads();
    #pragma unroll
    for (int q = 0; q < 3; ++q) {
        if (q >= ntc) break;
        int tile = nh ? 3 + q : q;
        int o = tile * 8 + (lane & 3) * 2;
        if (tile < 4) {
            out[(size_t)(r0 + r1) * 32 + o]     = acc2[q][0];
            out[(size_t)(r0 + r1) * 32 + o + 1] = acc2[q][1];
            out[(size_t)(r0 + r2) * 32 + o]     = acc2[q][2];
            out[(size_t)(r0 + r2) * 32 + o + 1] = acc2[q][3];
        } else if ((lane & 3) == 0) {
            float qcv = __ldg(qc);
            out[(size_t)BATCH * 32 + r0 + r1] = ys[r1] + acc2[q][0] + qcv;
            out[(size_t)BATCH * 32 + r0 + r2] = ys[r2] + acc2[q][2] + qcv;
        }
    }
}

// ---------------------------------------------------------------------------
extern "C" void kernel_launch(void* const* d_in, const int* in_sizes, int n_in,
                              void* d_out, int out_size) {
    const float* x  = (const float*)d_in[0];
    const float* W1 = (const float*)d_in[1];
    const float* b1 = (const float*)d_in[2];
    const float* W2 = (const float*)d_in[3];
    const float* Lv = (const float*)d_in[4];
    const float* qb = (const float*)d_in[5];
    const float* qc = (const float*)d_in[6];
    float* out = (float*)d_out;

    // Attribute set only on the (non-captured) first call — runtime APIs
    // during graph capture kill the capture (R5/R7 lesson).
    static bool attr_done = false;
    if (!attr_done) {
        cudaFuncSetAttribute(koopman_hmma,
                             cudaFuncAttributeMaxDynamicSharedMemorySize,
                             SMEM_TOTAL);
        attr_done = true;
    }

    prep_x   <<<2048, 256>>>(x);
    prep_rest<<<170,  256>>>(W1, Lv, W2, qb);
    koopman_hmma<<<NCTA, NT, SMEM_TOTAL>>>(b1, qc, out);
}